// round 9
// baseline (speedup 1.0000x reference)
#include <cuda_runtime.h>

// XdGate on site INDEX=3 of an L=8 qutrit (D=3) state vector, N = 3^8 = 6561.
//
// U = I x I x I x M x I x I x I x I with M|i> = |(3-i) mod 3> — a pure
// permutation of the site-3 trit (stride 3^4 = 81):
//   t=0 -> delta 0, t=1 -> +81, t=2 -> -81 (element offsets).
//
// TERMINAL VARIANT. Eight rounds of evidence: ncu kernel time 3.97-4.54us
// (+-0.3us noise), harness 5.02-6.08us (+-0.6us noise on identical binaries),
// issue <=10%, DRAM 0.1%, ALU/FMA pipes 0.0%. The kernel is a single-launch
// fixed-overhead floor; no body or grid change registers above noise.
// This combines the two best-measured structures:
//   - divide-free trit: 3D block (81, 3, 3) makes t = threadIdx.y directly
//   - minimal launch front: 9 blocks x 729 threads, exact cover of 6561
// idx = blockIdx.x*729 + z*243 + y*81 + x; no guard, no tail, regs <= 16.
// Vectorized 16B access impossible (src/dst differ by 81 elems = 4B mod 16);
// memcpy decompositions need >=3 graph nodes > 1 kernel node.

static constexpr int STRIDE = 81;   // 3^4

__global__ __launch_bounds__(729) void xd_gate_kernel(
    const float* __restrict__ x, float* __restrict__ out) {
    int t = threadIdx.y;                          // site-3 trit, directly: 0,1,2
    int d = (t == 1) - (t == 2);                  // 0 -> 0, 1 -> +1, 2 -> -1
    int idx = blockIdx.x * 729 + threadIdx.z * 243 + t * STRIDE + threadIdx.x;
    out[idx] = x[idx + d * STRIDE];
}

extern "C" void kernel_launch(void* const* d_in, const int* in_sizes, int n_in,
                              void* d_out, int out_size) {
    const float* x = (const float*)d_in[0];   // [6561, 1] float32
    // d_in[1] is M [3,3] — permutation baked in.
    float* out = (float*)d_out;

    dim3 block(81, 3, 3);                     // 729 threads; y = site-3 trit
    xd_gate_kernel<<<9, block>>>(x, out);     // 9 * 729 = 6561 exactly
}